// round 7
// baseline (speedup 1.0000x reference)
#include <cuda_runtime.h>
#include <cstdint>

// Problem constants
#define BATCH    16
#define HW       (1024 * 1024)
#define HW4      (HW / 4)
#define GRIDX    37            // 37*16 = 592 = 148 SMs * 4 CTAs -> one exact wave
#define NT       256
#define NQ       8             // g, tg, lg, omp, tomp, t, bin, bint
#define SMOOTH   1e-6f
#define NBLOCKS  (GRIDX * BATCH)

#define NSLOT    4
#define STRIDE   (GRIDX * NT)                          // 9472 float4s
#define NITER    ((HW4 + STRIDE - 1) / STRIDE)         // 28

__device__ float        g_part[BATCH * GRIDX * NQ];
__device__ unsigned int g_count;   // zero-init; self-resets each launch

typedef unsigned long long ull;

// ---------- f32x2 packed helpers ----------
__device__ __forceinline__ ull pk2(float lo, float hi) {
    ull r; asm("mov.b64 %0, {%1, %2};" : "=l"(r) : "f"(lo), "f"(hi)); return r;
}
__device__ __forceinline__ void upk2(ull v, float& lo, float& hi) {
    asm("mov.b64 {%0, %1}, %2;" : "=f"(lo), "=f"(hi) : "l"(v));
}
__device__ __forceinline__ ull mul2(ull a, ull b) {
    ull r; asm("mul.rn.f32x2 %0, %1, %2;" : "=l"(r) : "l"(a), "l"(b)); return r;
}
__device__ __forceinline__ ull add2(ull a, ull b) {
    ull r; asm("add.rn.f32x2 %0, %1, %2;" : "=l"(r) : "l"(a), "l"(b)); return r;
}
__device__ __forceinline__ ull fma2(ull a, ull b, ull c) {
    ull r; asm("fma.rn.f32x2 %0, %1, %2, %3;" : "=l"(r) : "l"(a), "l"(b), "l"(c)); return r;
}
__device__ __forceinline__ float ex2a(float x) {
    float r; asm("ex2.approx.f32 %0, %1;" : "=f"(r) : "f"(x)); return r;
}
__device__ __forceinline__ float lg2a(float x) {
    float r; asm("lg2.approx.f32 %0, %1;" : "=f"(r) : "f"(x)); return r;
}
__device__ __forceinline__ float rcpa(float x) {
    float r; asm("rcp.approx.f32 %0, %1;" : "=f"(r) : "f"(x)); return r;
}
__device__ __forceinline__ float setgt0(float x) {
    float r; asm("set.gt.f32.f32 %0, %1, 0f00000000;" : "=f"(r) : "f"(x)); return r;
}

// ---------- cp.async (LDGSTS) helpers ----------
__device__ __forceinline__ uint32_t smem_u32(const void* p) {
    uint32_t a;
    asm("{ .reg .u64 t; cvta.to.shared.u64 t, %1; cvt.u32.u64 %0, t; }" : "=r"(a) : "l"(p));
    return a;
}
__device__ __forceinline__ void cp16(uint32_t dst, const void* src) {
    asm volatile("cp.async.cg.shared.global [%0], [%1], 16;"
                 :: "r"(dst), "l"(src) : "memory");
}
__device__ __forceinline__ void cp_commit() {
    asm volatile("cp.async.commit_group;" ::: "memory");
}
__device__ __forceinline__ void cp_wait2() {
    asm volatile("cp.async.wait_group 2;" ::: "memory");
}

struct Accs { ull g, tg, lg, omp, tomp, t, bin, bint; };

// Per-pair math, t in {0,1}:
//   v = exp((1-2t)x) ; ce = ln2*lg2(1+v) ; omp = 1-p_t = v/(1+v)
__device__ __forceinline__ void group(Accs& A, float x0, float x1, float t0, float t1,
                                      ull Kp, ull Km2, ull ONE2) {
    ull x2 = pk2(x0, x1);
    ull t2 = pk2(t0, t1);
    ull c2 = fma2(t2, Km2, Kp);          // log2e * (1-2t)
    ull m2 = mul2(x2, c2);
    float m0, m1; upk2(m2, m0, m1);
    float v0 = ex2a(m0), v1 = ex2a(m1);
    ull v2 = pk2(v0, v1);
    ull s2 = add2(v2, ONE2);             // 1+v
    float s0, s1; upk2(s2, s0, s1);
    float r0 = rcpa(s0), r1 = rcpa(s1);
    float l0 = lg2a(s0), l1 = lg2a(s1);
    ull r2 = pk2(r0, r1);
    ull l2 = pk2(l0, l1);
    ull omp2 = mul2(v2, r2);
    ull o2   = mul2(omp2, omp2);
    ull g2   = mul2(l2, o2);
    A.g    = add2(A.g, g2);
    A.tg   = fma2(t2, g2, A.tg);
    A.lg   = add2(A.lg, l2);
    A.omp  = add2(A.omp, omp2);
    A.tomp = fma2(t2, omp2, A.tomp);
    A.t    = add2(A.t, t2);
    ull bin2 = pk2(setgt0(x0), setgt0(x1));
    A.bin  = add2(A.bin, bin2);
    A.bint = fma2(t2, bin2, A.bint);
}

__device__ __forceinline__ float warp_sum(float v) {
    #pragma unroll
    for (int off = 16; off > 0; off >>= 1)
        v += __shfl_xor_sync(0xFFFFFFFFu, v, off);
    return v;
}

__global__ __launch_bounds__(NT, 4)
void loss_fused_kernel(const float4* __restrict__ pred,
                       const float4* __restrict__ gt,
                       const float*  __restrict__ pred_iou,
                       float*        __restrict__ out) {
    // Per-thread private staging: [array][slot][tid] 16B each -> 32 KB total
    __shared__ float4 st_p[NSLOT][NT];
    __shared__ float4 st_g[NSLOT][NT];

    const int tid = threadIdx.x;
    const int img = blockIdx.y;

    const float4* pimg = pred + (size_t)img * HW4;
    const float4* gimg = gt   + (size_t)img * HW4;

    const uint32_t spb = smem_u32(&st_p[0][tid]);   // + slot*4096
    const uint32_t sgb = smem_u32(&st_g[0][tid]);

    const int base = blockIdx.x * NT + tid;

    // prologue: stage slots 0..2
    #pragma unroll
    for (int j = 0; j < NSLOT - 1; j++) {
        int idx = base + j * STRIDE;
        if (idx < HW4) {
            cp16(spb + (uint32_t)j * (NT * 16), pimg + idx);
            cp16(sgb + (uint32_t)j * (NT * 16), gimg + idx);
        }
        cp_commit();
    }

    const float LOG2E = 1.4426950408889634f;
    const ull Kp   = pk2(LOG2E, LOG2E);
    const ull Km2  = pk2(-2.0f * LOG2E, -2.0f * LOG2E);
    const ull ONE2 = pk2(1.0f, 1.0f);

    Accs A;
    A.g = A.tg = A.lg = A.omp = A.tomp = A.t = A.bin = A.bint = pk2(0.0f, 0.0f);

    #pragma unroll 4
    for (int j = 0; j < NITER; j++) {
        cp_wait2();                          // slot j's group complete
        const int slot = j & (NSLOT - 1);
        const int idx  = base + j * STRIDE;

        float4 p4, g4;
        bool valid = (idx < HW4);
        if (valid) {
            p4 = st_p[slot][tid];
            g4 = st_g[slot][tid];
        }

        // prefetch 3 ahead into slot (j+3)&3 (free: consumed at iter j-1)
        const int jn   = j + NSLOT - 1;
        const int idxn = base + jn * STRIDE;
        if (idxn < HW4) {
            const uint32_t soff = (uint32_t)(jn & (NSLOT - 1)) * (NT * 16);
            cp16(spb + soff, pimg + idxn);
            cp16(sgb + soff, gimg + idxn);
        }
        cp_commit();

        if (valid) {
            group(A, p4.x, p4.y, g4.x, g4.y, Kp, Km2, ONE2);
            group(A, p4.z, p4.w, g4.z, g4.w, Kp, Km2, ONE2);
        }
    }

    // collapse packed halves
    float vals[NQ];
    {
        float lo, hi;
        upk2(A.g,    lo, hi); vals[0] = lo + hi;
        upk2(A.tg,   lo, hi); vals[1] = lo + hi;
        upk2(A.lg,   lo, hi); vals[2] = lo + hi;
        upk2(A.omp,  lo, hi); vals[3] = lo + hi;
        upk2(A.tomp, lo, hi); vals[4] = lo + hi;
        upk2(A.t,    lo, hi); vals[5] = lo + hi;
        upk2(A.bin,  lo, hi); vals[6] = lo + hi;
        upk2(A.bint, lo, hi); vals[7] = lo + hi;
    }

    // -------- block reduction --------
    #pragma unroll
    for (int q = 0; q < NQ; q++) vals[q] = warp_sum(vals[q]);

    __shared__ float sm[NT / 32][NQ];
    const int lane = tid & 31;
    const int warp = tid >> 5;
    if (lane == 0) {
        #pragma unroll
        for (int q = 0; q < NQ; q++) sm[warp][q] = vals[q];
    }
    __syncthreads();

    __shared__ bool is_last;
    if (warp == 0) {
        #pragma unroll
        for (int q = 0; q < NQ; q++) {
            float v = (lane < NT / 32) ? sm[lane][q] : 0.0f;
            v = warp_sum(v);
            if (lane == 0) vals[q] = v;
        }
        if (lane == 0) {
            float* dst = g_part + ((size_t)img * GRIDX + blockIdx.x) * NQ;
            #pragma unroll
            for (int q = 0; q < NQ; q++) dst[q] = vals[q];
            __threadfence();
            unsigned int v = atomicAdd(&g_count, 1u);
            is_last = (v == (unsigned int)(NBLOCKS - 1));
        }
    }
    __syncthreads();
    if (!is_last) return;

    // -------- epilogue: last block reduces 592 partials --------
    __shared__ float agg[BATCH][4];
    for (int b = warp; b < BATCH; b += NT / 32) {
        float s[NQ] = {0.f, 0.f, 0.f, 0.f, 0.f, 0.f, 0.f, 0.f};
        for (int j = lane; j < GRIDX; j += 32) {
            const float* q = g_part + ((size_t)b * GRIDX + j) * NQ;
            #pragma unroll
            for (int k = 0; k < NQ; k++) s[k] += q[k];
        }
        #pragma unroll
        for (int k = 0; k < NQ; k++) s[k] = warp_sum(s[k]);
        if (lane == 0) {
            // s: 0=g 1=tg 2=lg 3=omp 4=tomp 5=t 6=bin 7=bint
            float Sp  = s[3] + s[5] - 2.0f * s[4];
            float Spt = s[5] - s[4];
            float dice_term = (2.0f * Spt + SMOOTH) / (Sp + s[5] + SMOOTH);
            float inter  = s[7];
            float uni    = s[6] + s[5] - s[7];
            float actual = (inter + SMOOTH) / (uni + SMOOTH);
            float d = pred_iou[b] - actual;
            agg[b][0] = 0.75f * s[0] - 0.5f * s[1];
            agg[b][1] = s[2];
            agg[b][2] = dice_term;
            agg[b][3] = d * d;
        }
    }
    __syncthreads();

    if (tid == 0) {
        float fsum = 0.f, csum = 0.f, dsum = 0.f, isum = 0.f;
        #pragma unroll
        for (int b = 0; b < BATCH; b++) {
            fsum += agg[b][0];
            csum += agg[b][1];
            dsum += agg[b][2];
            isum += agg[b][3];
        }
        const float LN2  = 0.6931471805599453f;
        const float invN = 1.0f / (float)((long long)BATCH * HW);
        float focal    = LN2 * fsum * invN;
        float dice     = 1.0f - dsum / (float)BATCH;
        float boundary = LN2 * csum * invN;
        float iou_loss = 0.1f * (isum / (float)BATCH);
        out[0] = focal + dice + boundary + iou_loss;
        g_count = 0;
    }
}

extern "C" void kernel_launch(void* const* d_in, const int* in_sizes, int n_in,
                              void* d_out, int out_size) {
    const float4* pred = (const float4*)d_in[0];
    const float4* gt   = (const float4*)d_in[1];
    const float*  piou = (const float*)d_in[2];
    float* out = (float*)d_out;

    dim3 grid(GRIDX, BATCH);
    loss_fused_kernel<<<grid, NT>>>(pred, gt, piou, out);
}